// round 3
// baseline (speedup 1.0000x reference)
#include <cuda_runtime.h>
#include <math.h>

#define BATCH 128
#define NDOC  8
#define LQ    32
#define LD    256
#define DIM   128
#define NEGV  (-9999.0f)

#define KT    64
#define PITCH 129   // odd pitch -> conflict-free scalar LDS on d-rows

// Scratch (no allocations allowed)
__device__ float g_qn[(size_t)BATCH * DIM * LQ];      // normalized q, transposed: [b][d][q]
__device__ float g_scores[2 * BATCH * NDOC];          // [mat][b][n]

// ---------------------------------------------------------------------------
// Kernel 1: normalize q rows over D, write transposed [b][d][q]
// ---------------------------------------------------------------------------
__global__ __launch_bounds__(128) void qnorm_kernel(const float* __restrict__ q)
{
    __shared__ float sq[LQ * PITCH];
    __shared__ float sInv[LQ];

    const int b    = blockIdx.x;
    const int t    = threadIdx.x;        // 128 threads
    const int lane = t & 31;
    const int w    = t >> 5;             // 4 warps

    const float* qb = q + (size_t)b * LQ * DIM;

    // Load 32x128 floats (1024 float4) into smem, pitch 129
#pragma unroll
    for (int i = 0; i < 8; i++) {
        int idx = i * 128 + t;           // float4 index
        float4 v = ((const float4*)qb)[idx];
        int l = idx >> 5;                // 32 float4 per row
        int d = (idx & 31) * 4;
        float* s = &sq[l * PITCH + d];
        s[0] = v.x; s[1] = v.y; s[2] = v.z; s[3] = v.w;
    }
    __syncthreads();

    // warp w: rows 8w..8w+7
#pragma unroll
    for (int rr = 0; rr < 8; rr++) {
        int r = w * 8 + rr;
        const float* s = &sq[r * PITCH + lane * 4];
        float ss = s[0]*s[0] + s[1]*s[1] + s[2]*s[2] + s[3]*s[3];
        ss += __shfl_xor_sync(0xffffffffu, ss, 16);
        ss += __shfl_xor_sync(0xffffffffu, ss, 8);
        ss += __shfl_xor_sync(0xffffffffu, ss, 4);
        ss += __shfl_xor_sync(0xffffffffu, ss, 2);
        ss += __shfl_xor_sync(0xffffffffu, ss, 1);
        if (lane == 0) sInv[r] = 1.0f / fmaxf(sqrtf(ss), 1e-12f);
    }
    __syncthreads();

    // Write transposed [d][q], coalesced over output
    float* out = g_qn + (size_t)b * DIM * LQ;
#pragma unroll
    for (int i = 0; i < 32; i++) {
        int o = i * 128 + t;
        int d = o >> 5;
        int l = o & 31;
        out[o] = sq[l * PITCH + d] * sInv[l];
    }
}

// ---------------------------------------------------------------------------
// Kernel 2: per-(n,b,matrix) MaxSim score:
//   score = sum_q max_k ( mask[k] ? dot(qn[b,q], d[n,b,k]) / ||d[n,b,k]|| : NEG )
// grid.x = N*B (nb = n*B+b), grid.y = matrix (0: d_cq, 1: d_orig), 256 threads
// ---------------------------------------------------------------------------
__global__ __launch_bounds__(256) void maxsim_kernel(
    const float* __restrict__ d_cq,
    const float* __restrict__ d_orig,
    const int*   __restrict__ dmask)
{
    __shared__ float sD[KT * PITCH];     // d tile, row-major, pitch 129
    __shared__ float sQc[32 * 32];       // q chunk: [dd][q]
    __shared__ float sSS[KT];
    __shared__ float sInv[KT];
    __shared__ float sRed[8];

    const int nb = blockIdx.x;           // n*BATCH + b
    const int b  = nb & (BATCH - 1);
    const int n  = nb >> 7;

    const float* dmat  = (blockIdx.y == 0) ? d_cq : d_orig;
    const float* dbase = dmat + (size_t)nb * LD * DIM;
    const int*   mbase = dmask + nb * LD;
    const float* qb    = g_qn + (size_t)b * DIM * LQ;

    const int t    = threadIdx.x;
    const int lane = t & 31;
    const int w    = t >> 5;             // 8 warps = 8 q-groups of 4
    const int l8   = lane >> 3;          // 0..3  (row offset within load)
    const int m8   = lane & 7;           // 0..7  (col group within load)

    float qmax0 = NEGV, qmax1 = NEGV, qmax2 = NEGV, qmax3 = NEGV;

    for (int tile = 0; tile < LD / KT; tile++) {
        const int k0 = tile * KT;
        __syncthreads();                  // prev tile fully consumed

        // ---- load d tile (64 rows x 128) with fused sum-of-squares ----
        // warp w owns rows [w*8, w*8+8). Lane mapping (4 rows x 8 col-groups)
        // makes both global loads (4x128B rows) and smem stores conflict-free.
        float ssA = 0.f, ssB = 0.f;
#pragma unroll
        for (int i = 0; i < 8; i++) {
            int half = i >> 2;            // 0: rows +0..3, 1: rows +4..7
            int ph   = i & 3;
            int k    = w * 8 + half * 4 + l8;
            int f4   = ph * 8 + m8;
            float4 v = ((const float4*)(dbase + (size_t)(k0 + k) * DIM))[f4];
            float* s = &sD[k * PITCH + f4 * 4];
            s[0] = v.x; s[1] = v.y; s[2] = v.z; s[3] = v.w;
            float ss = v.x*v.x + v.y*v.y + v.z*v.z + v.w*v.w;
            if (half == 0) ssA += ss; else ssB += ss;
        }
        // reduce sumsq within the 8 lanes sharing each row (bits 0..2 of lane)
        ssA += __shfl_xor_sync(0xffffffffu, ssA, 1);
        ssA += __shfl_xor_sync(0xffffffffu, ssA, 2);
        ssA += __shfl_xor_sync(0xffffffffu, ssA, 4);
        ssB += __shfl_xor_sync(0xffffffffu, ssB, 1);
        ssB += __shfl_xor_sync(0xffffffffu, ssB, 2);
        ssB += __shfl_xor_sync(0xffffffffu, ssB, 4);
        if (m8 == 0) {
            sSS[w * 8 + l8]     = ssA;
            sSS[w * 8 + 4 + l8] = ssB;
        }
        __syncthreads();
        if (t < KT) {
            int m = mbase[k0 + t];
            sInv[t] = m ? (1.0f / fmaxf(sqrtf(sSS[t]), 1e-12f)) : 0.0f;
        }

        // ---- GEMM accumulation: acc[4q][2k], k = lane and lane+32 ----
        float a00=0.f,a01=0.f,a10=0.f,a11=0.f,a20=0.f,a21=0.f,a30=0.f,a31=0.f;
        for (int ch = 0; ch < 4; ch++) {
            __syncthreads();              // also orders sInv writes (ch==0)
            // load q chunk [32 dd][32 q], contiguous 4KB, L2-resident
            ((float4*)sQc)[t] = ((const float4*)(qb + ch * 32 * 32))[t];
            __syncthreads();

            const float* dr0 = &sD[lane * PITCH + ch * 32];
            const float* dr1 = &sD[(lane + 32) * PITCH + ch * 32];
            const float* qc  = sQc + w * 4;
#pragma unroll
            for (int dd = 0; dd < 32; dd++) {
                float d0 = dr0[dd];       // bank = lane+dd : conflict-free
                float d1 = dr1[dd];
                float4 qv = *(const float4*)(qc + dd * 32);  // warp broadcast
                a00 += qv.x * d0;  a01 += qv.x * d1;
                a10 += qv.y * d0;  a11 += qv.y * d1;
                a20 += qv.z * d0;  a21 += qv.z * d1;
                a30 += qv.w * d0;  a31 += qv.w * d1;
            }
        }

        // ---- epilogue: scale by invnorm, mask -> NEG, running max over k ----
        float inv0 = sInv[lane];
        float inv1 = sInv[lane + 32];
        float s00 = (inv0 != 0.f) ? a00 * inv0 : NEGV;
        float s01 = (inv1 != 0.f) ? a01 * inv1 : NEGV;
        float s10 = (inv0 != 0.f) ? a10 * inv0 : NEGV;
        float s11 = (inv1 != 0.f) ? a11 * inv1 : NEGV;
        float s20 = (inv0 != 0.f) ? a20 * inv0 : NEGV;
        float s21 = (inv1 != 0.f) ? a21 * inv1 : NEGV;
        float s30 = (inv0 != 0.f) ? a30 * inv0 : NEGV;
        float s31 = (inv1 != 0.f) ? a31 * inv1 : NEGV;
        qmax0 = fmaxf(qmax0, fmaxf(s00, s01));
        qmax1 = fmaxf(qmax1, fmaxf(s10, s11));
        qmax2 = fmaxf(qmax2, fmaxf(s20, s21));
        qmax3 = fmaxf(qmax3, fmaxf(s30, s31));
    }

    // max over all k (lanes), then sum over this warp's 4 q-rows
#pragma unroll
    for (int off = 16; off >= 1; off >>= 1) {
        qmax0 = fmaxf(qmax0, __shfl_xor_sync(0xffffffffu, qmax0, off));
        qmax1 = fmaxf(qmax1, __shfl_xor_sync(0xffffffffu, qmax1, off));
        qmax2 = fmaxf(qmax2, __shfl_xor_sync(0xffffffffu, qmax2, off));
        qmax3 = fmaxf(qmax3, __shfl_xor_sync(0xffffffffu, qmax3, off));
    }
    if (lane == 0) sRed[w] = qmax0 + qmax1 + qmax2 + qmax3;
    __syncthreads();
    if (t == 0) {
        float s = 0.f;
#pragma unroll
        for (int i = 0; i < 8; i++) s += sRed[i];
        g_scores[blockIdx.y * (BATCH * NDOC) + b * NDOC + n] = s;
    }
}

// ---------------------------------------------------------------------------
// Kernel 3: KL(log_softmax(teacher) || log_softmax(student)), batchmean
// ---------------------------------------------------------------------------
__global__ __launch_bounds__(128) void loss_kernel(float* __restrict__ out)
{
    __shared__ float red[128];
    const int b = threadIdx.x;
    const float* s = g_scores + b * NDOC;                  // student (d_cq)
    const float* tt = g_scores + BATCH * NDOC + b * NDOC;  // teacher (d_orig)

    float sv[NDOC], tv[NDOC];
    float ms = -1e30f, mt = -1e30f;
#pragma unroll
    for (int i = 0; i < NDOC; i++) {
        sv[i] = s[i]; tv[i] = tt[i];
        ms = fmaxf(ms, sv[i]); mt = fmaxf(mt, tv[i]);
    }
    float es = 0.f, et = 0.f;
#pragma unroll
    for (int i = 0; i < NDOC; i++) {
        es += expf(sv[i] - ms);
        et += expf(tv[i] - mt);
    }
    float lse_s = logf(es), lse_t = logf(et);
    float kl = 0.f;
#pragma unroll
    for (int i = 0; i < NDOC; i++) {
        float lti = tv[i] - mt - lse_t;
        float lsi = sv[i] - ms - lse_s;
        kl += expf(lti) * (lti - lsi);
    }
    red[b] = kl;
    __syncthreads();
#pragma unroll
    for (int off = 64; off >= 1; off >>= 1) {
        if (b < off) red[b] += red[b + off];
        __syncthreads();
    }
    if (b == 0) out[0] = red[0] / (float)BATCH;
}

// ---------------------------------------------------------------------------
extern "C" void kernel_launch(void* const* d_in, const int* in_sizes, int n_in,
                              void* d_out, int out_size)
{
    (void)in_sizes; (void)n_in; (void)out_size;
    const float* q_reps = (const float*)d_in[0];
    const float* d_cq   = (const float*)d_in[1];
    const float* d_orig = (const float*)d_in[2];
    const int*   d_mask = (const int*)d_in[3];
    // d_in[4] = labels (unused by the reference loss path)

    qnorm_kernel<<<BATCH, 128>>>(q_reps);
    maxsim_kernel<<<dim3(NDOC * BATCH, 2), 256>>>(d_cq, d_orig, d_mask);
    loss_kernel<<<1, 128>>>((float*)d_out);
}

// round 8
// speedup vs baseline: 1.2423x; 1.2423x over previous
#include <cuda_runtime.h>
#include <cuda_bf16.h>
#include <math.h>
#include <cstdint>

#define BATCH 128
#define NDOC  8
#define LQ    32
#define LD    256
#define DIM   128
#define NEGV  (-9999.0f)
#define QPITCH 129

// A/B smem row pitch in bytes (128 bf16 = 256B data + 16B pad).
// 272 = 16*17: 16B-aligned; ldmatrix rows r -> bank 4r mod 32: conflict-free.
#define APITCH 272
#define APITCH_U32 68

// dynamic smem layout (bytes)
#define SM_AHI  0                      // 128 x 272  = 34816
#define SM_ALO  34816                  // 128 x 272  = 34816
#define SM_BHI  69632                  // 32  x 272  =  8704
#define SM_BLO  78336                  // 32  x 272  =  8704
#define SM_SS   87040                  // 128 f32    =   512
#define SM_INV  87552                  // 128 f32    =   512
#define SM_MAX  88064                  // 8 x 32 f32 =  1024
#define SMEM_TOTAL 89088

// scratch (no allocations allowed)
__device__ unsigned g_qhi[(size_t)BATCH * 2048];   // per-b [32][64] u32 (bf16x2 hi)
__device__ unsigned g_qlo[(size_t)BATCH * 2048];   // per-b [32][64] u32 (bf16x2 lo)
__device__ float    g_scores[2 * BATCH * NDOC];    // [mat][b][n]

// ---------------------------------------------------------------------------
__device__ __forceinline__ uint32_t smem_u32(const void* p) {
    uint32_t a;
    asm("{ .reg .u64 t; cvta.to.shared.u64 t, %1; cvt.u32.u64 %0, t; }" : "=r"(a) : "l"(p));
    return a;
}

// split two floats into bf16x2 hi pair + bf16x2 lo pair (x in low half)
__device__ __forceinline__ void split2(float x, float y, unsigned& hi2, unsigned& lo2) {
    asm("cvt.rn.bf16x2.f32 %0, %1, %2;" : "=r"(hi2) : "f"(y), "f"(x));
    float hx = __uint_as_float(hi2 << 16);
    float hy = __uint_as_float(hi2 & 0xFFFF0000u);
    float lx = x - hx, ly = y - hy;
    asm("cvt.rn.bf16x2.f32 %0, %1, %2;" : "=r"(lo2) : "f"(ly), "f"(lx));
}

__device__ __forceinline__ void ldmatrix_x4(uint32_t addr, uint32_t& r0, uint32_t& r1,
                                            uint32_t& r2, uint32_t& r3) {
    asm volatile("ldmatrix.sync.aligned.m8n8.x4.shared.b16 {%0,%1,%2,%3}, [%4];"
                 : "=r"(r0), "=r"(r1), "=r"(r2), "=r"(r3) : "r"(addr));
}

__device__ __forceinline__ void mma_bf16(float* c, const uint32_t* a, uint32_t b0, uint32_t b1) {
    asm volatile(
        "mma.sync.aligned.m16n8k16.row.col.f32.bf16.bf16.f32 "
        "{%0,%1,%2,%3}, {%4,%5,%6,%7}, {%8,%9}, {%0,%1,%2,%3};"
        : "+f"(c[0]), "+f"(c[1]), "+f"(c[2]), "+f"(c[3])
        : "r"(a[0]), "r"(a[1]), "r"(a[2]), "r"(a[3]), "r"(b0), "r"(b1));
}

// ---------------------------------------------------------------------------
// Kernel 1: normalize q rows, split to bf16 hi/lo, store compact [32][64] u32
// ---------------------------------------------------------------------------
__global__ __launch_bounds__(128) void qnorm_kernel(const float* __restrict__ q)
{
    __shared__ float sq[LQ * QPITCH];
    __shared__ float sInv[LQ];

    const int b = blockIdx.x, t = threadIdx.x;
    const int lane = t & 31, w = t >> 5;
    const float* qb = q + (size_t)b * LQ * DIM;

#pragma unroll
    for (int i = 0; i < 8; i++) {
        int idx = i * 128 + t;
        float4 v = ((const float4*)qb)[idx];
        int l = idx >> 5, d = (idx & 31) * 4;
        float* s = &sq[l * QPITCH + d];
        s[0] = v.x; s[1] = v.y; s[2] = v.z; s[3] = v.w;
    }
    __syncthreads();

#pragma unroll
    for (int rr = 0; rr < 8; rr++) {
        int r = w * 8 + rr;
        const float* s = &sq[r * QPITCH + lane * 4];
        float ss = s[0]*s[0] + s[1]*s[1] + s[2]*s[2] + s[3]*s[3];
        ss += __shfl_xor_sync(0xffffffffu, ss, 16);
        ss += __shfl_xor_sync(0xffffffffu, ss, 8);
        ss += __shfl_xor_sync(0xffffffffu, ss, 4);
        ss += __shfl_xor_sync(0xffffffffu, ss, 2);
        ss += __shfl_xor_sync(0xffffffffu, ss, 1);
        if (lane == 0) sInv[r] = 1.0f / fmaxf(sqrtf(ss), 1e-12f);
    }
    __syncthreads();

    const int qr = t >> 2, c = t & 3;        // row 0..31, col-quarter 0..3
    const float inv = sInv[qr];
    unsigned* oh = g_qhi + (size_t)b * 2048;
    unsigned* ol = g_qlo + (size_t)b * 2048;
#pragma unroll
    for (int i = 0; i < 16; i++) {
        int j = c * 16 + i;                  // u32 index 0..63 (cols 2j, 2j+1)
        float x = sq[qr * QPITCH + 2 * j] * inv;
        float y = sq[qr * QPITCH + 2 * j + 1] * inv;
        unsigned hi2, lo2;
        split2(x, y, hi2, lo2);
        oh[qr * 64 + j] = hi2;
        ol[qr * 64 + j] = lo2;
    }
}

// ---------------------------------------------------------------------------
// Kernel 2: split-bf16 HMMA MaxSim. One CTA per (nb, matrix). 256 threads.
// ---------------------------------------------------------------------------
__global__ __launch_bounds__(256) void maxsim_mma_kernel(
    const float* __restrict__ d_cq,
    const float* __restrict__ d_orig,
    const int*   __restrict__ dmask)
{
    extern __shared__ char smem[];
    const uint32_t sb = smem_u32(smem);

    const int nb = blockIdx.x;
    const int b  = nb & (BATCH - 1);
    const int n  = nb >> 7;
    const float* dmat  = (blockIdx.y == 0) ? d_cq : d_orig;
    const float* dbase = dmat + (size_t)nb * LD * DIM;
    const int*   mbase = dmask + nb * LD;

    const int t = threadIdx.x;
    const int lane = t & 31, w = t >> 5;     // 8 warps

    float* sInv = (float*)(smem + SM_INV);
    float* sSS  = (float*)(smem + SM_SS);
    float* sMax = (float*)(smem + SM_MAX);

    // ---- copy q tiles into padded smem [32][APITCH] ----
    {
        const unsigned* sh = g_qhi + (size_t)b * 2048;
        const unsigned* sl = g_qlo + (size_t)b * 2048;
        unsigned* dh = (unsigned*)(smem + SM_BHI);
        unsigned* dl = (unsigned*)(smem + SM_BLO);
#pragma unroll
        for (int i = 0; i < 8; i++) {
            int idx = i * 256 + t;           // 0..2047
            int row = idx >> 6, col = idx & 63;
            dh[row * APITCH_U32 + col] = sh[idx];
            dl[row * APITCH_U32 + col] = sl[idx];
        }
    }

    // per-thread running max for 8 q-cols: cols j*8 + 2*(lane&3) + {0,1}
    float rm[4][2];
#pragma unroll
    for (int j = 0; j < 4; j++) { rm[j][0] = NEGV; rm[j][1] = NEGV; }

    const int row2 = t >> 1;                 // 0..127 (load row)
    const int side = t & 1;                  // half-row

    for (int half = 0; half < 2; half++) {
        if (half) __syncthreads();           // prev half fully consumed
        const float* dh = dbase + (size_t)half * 128 * DIM;

        // ---- load 128x128 fp32: fused sumsq + split + padded smem store ----
        {
            const float4* rp = (const float4*)(dh + (size_t)row2 * DIM);
            char* ah = smem + SM_AHI + row2 * APITCH;
            char* al = smem + SM_ALO + row2 * APITCH;
            float ss = 0.f;
#pragma unroll
            for (int i = 0; i < 16; i++) {
                int f4 = side * 16 + i;      // float4 index 0..31
                float4 v = rp[f4];
                ss += v.x*v.x + v.y*v.y + v.z*v.z + v.w*v.w;
                unsigned h0, l0, h1, l1;
                split2(v.x, v.y, h0, l0);
                split2(v.z, v.w, h1, l1);
                *(uint2*)(ah + f4 * 8) = make_uint2(h0, h1);
                *(uint2*)(al + f4 * 8) = make_uint2(l0, l1);
            }
            ss += __shfl_xor_sync(0xffffffffu, ss, 1);
            if (side == 0) sSS[row2] = ss;
        }
        __syncthreads();

        if (t < 128) {
            int m = mbase[half * 128 + t];
            sInv[t] = m ? (1.0f / fmaxf(sqrtf(sSS[t]), 1e-12f)) : 0.0f;
        }
        __syncthreads();

        // ---- MMA: warp w owns doc rows w*16 .. w*16+15 ----
        float acc[4][4];
#pragma unroll
        for (int j = 0; j < 4; j++)
#pragma unroll
            for (int r = 0; r < 4; r++) acc[j][r] = 0.f;

        const uint32_t aRow = (uint32_t)(w * 16 + (lane & 15)) * APITCH + (uint32_t)(lane >> 4) * 16;
        const uint32_t aHi = sb + SM_AHI + aRow;
        const uint32_t aLo = sb + SM_ALO + aRow;
        const uint32_t bOff = (uint32_t)(lane >> 2) * APITCH + (uint32_t)(lane & 3) * 4;

#pragma unroll
        for (int ks = 0; ks < 8; ks++) {
            uint32_t ah[4], al[4];
            ldmatrix_x4(aHi + ks * 32, ah[0], ah[1], ah[2], ah[3]);
            ldmatrix_x4(aLo + ks * 32, al[0], al[1], al[2], al[3]);
#pragma unroll
            for (int j = 0; j < 4; j++) {
                const uint32_t bo = bOff + (uint32_t)j * 8 * APITCH + (uint32_t)ks * 32;
                uint32_t bh0, bh1, bl0, bl1;
                asm volatile("ld.shared.b32 %0, [%1];"      : "=r"(bh0) : "r"(sb + SM_BHI + bo));
                asm volatile("ld.shared.b32 %0, [%1];"      : "=r"(bh1) : "r"(sb + SM_BHI + bo + 16));
                asm volatile("ld.shared.b32 %0, [%1];"      : "=r"(bl0) : "r"(sb + SM_BLO + bo));
                asm volatile("ld.shared.b32 %0, [%1];"      : "=r"(bl1) : "r"(sb + SM_BLO + bo + 16));
                mma_bf16(acc[j], ah, bh0, bh1);   // hi * hi
                mma_bf16(acc[j], ah, bl0, bl1);   // hi * lo
                mma_bf16(acc[j], al, bh0, bh1);   // lo * hi
            }
        }

        // ---- epilogue: scale, mask, reduce over this warp's 16 rows ----
        const int r0 = w * 16 + (lane >> 2);
        const float inv0 = sInv[r0];
        const float inv1 = sInv[r0 + 8];
#pragma unroll
        for (int j = 0; j < 4; j++) {
            float s0 = (inv0 != 0.f) ? acc[j][0] * inv0 : NEGV;
            float s1 = (inv0 != 0.f) ? acc[j][1] * inv0 : NEGV;
            float s2 = (inv1 != 0.f) ? acc[j][2] * inv1 : NEGV;
            float s3 = (inv1 != 0.f) ? acc[j][3] * inv1 : NEGV;
            float m0 = fmaxf(s0, s2);
            float m1 = fmaxf(s1, s3);
            // max over the 8 groupIDs (row groups) -> per-q-col max for this warp
            m0 = fmaxf(m0, __shfl_xor_sync(0xffffffffu, m0, 4));
            m0 = fmaxf(m0, __shfl_xor_sync(0xffffffffu, m0, 8));
            m0 = fmaxf(m0, __shfl_xor_sync(0xffffffffu, m0, 16));
            m1 = fmaxf(m1, __shfl_xor_sync(0xffffffffu, m1, 4));
            m1 = fmaxf(m1, __shfl_xor_sync(0xffffffffu, m1, 8));
            m1 = fmaxf(m1, __shfl_xor_sync(0xffffffffu, m1, 16));
            rm[j][0] = fmaxf(rm[j][0], m0);
            rm[j][1] = fmaxf(rm[j][1], m1);
        }
    }

    // ---- cross-warp: per-q max over 8 warps, then sum over 32 q ----
    if (lane < 4) {
#pragma unroll
        for (int j = 0; j < 4; j++) {
            sMax[w * 32 + j * 8 + 2 * lane]     = rm[j][0];
            sMax[w * 32 + j * 8 + 2 * lane + 1] = rm[j][1];
        }
    }
    __syncthreads();
    if (w == 0) {
        float m = NEGV;
#pragma unroll
        for (int i = 0; i < 8; i++) m = fmaxf(m, sMax[i * 32 + lane]);
        m += __shfl_xor_sync(0xffffffffu, m, 16);
        m += __shfl_xor_sync(0xffffffffu, m, 8);
        m += __shfl_xor_sync(0xffffffffu, m, 4);
        m += __shfl_xor_sync(0xffffffffu, m, 2);
        m += __shfl_xor_sync(0xffffffffu, m, 1);
        if (lane == 0) g_scores[blockIdx.y * (BATCH * NDOC) + b * NDOC + n] = m;
    }
}

// ---------------------------------------------------------------------------
// Kernel 3: KL(log_softmax(teacher) || log_softmax(student)), batchmean
// ---------------------------------------------------------------------------
__global__ __launch_bounds__(128) void loss_kernel(float* __restrict__ out)
{
    __shared__ float red[128];
    const int b = threadIdx.x;
    const float* s  = g_scores + b * NDOC;
    const float* tt = g_scores + BATCH * NDOC + b * NDOC;

    float sv[NDOC], tv[NDOC];
    float ms = -1e30f, mt = -1e30f;
#pragma unroll
    for (int i = 0; i < NDOC; i++) {
        sv[i] = s[i]; tv[i] = tt[i];
        ms = fmaxf(ms, sv[i]); mt = fmaxf(mt, tv[i]);
    }
    float es = 0.f, et = 0.f;
#pragma unroll
    for (int i = 0; i < NDOC; i++) { es += expf(sv[i] - ms); et += expf(tv[i] - mt); }
    float lse_s = logf(es), lse_t = logf(et);
    float kl = 0.f;
#pragma unroll
    for (int i = 0; i < NDOC; i++) {
        float lti = tv[i] - mt - lse_t;
        float lsi = sv[i] - ms - lse_s;
        kl += expf(lti) * (lti - lsi);
    }
    red[b] = kl;
    __syncthreads();
#pragma unroll
    for (int off = 64; off >= 1; off >>= 1) {
        if (b < off) red[b] += red[b + off];
        __syncthreads();
    }
    if (b == 0) out[0] = red[0] / (float)BATCH;
}

// ---------------------------------------------------------------------------
extern "C" void kernel_launch(void* const* d_in, const int* in_sizes, int n_in,
                              void* d_out, int out_size)
{
    (void)in_sizes; (void)n_in; (void)out_size;
    const float* q_reps = (const float*)d_in[0];
    const float* d_cq   = (const float*)d_in[1];
    const float* d_orig = (const float*)d_in[2];
    const int*   d_mask = (const int*)d_in[3];

    cudaFuncSetAttribute(maxsim_mma_kernel,
                         cudaFuncAttributeMaxDynamicSharedMemorySize, SMEM_TOTAL);

    qnorm_kernel<<<BATCH, 128>>>(q_reps);
    maxsim_mma_kernel<<<dim3(NDOC * BATCH, 2), 256, SMEM_TOTAL>>>(d_cq, d_orig, d_mask);
    loss_kernel<<<1, 128>>>((float*)d_out);
}